// round 1
// baseline (speedup 1.0000x reference)
#include <cuda_runtime.h>
#include <math.h>

// Problem constants
#define NM 64          // molecules
#define NA 24          // atoms
#define NP 276         // descriptor pairs = 24*23/2
#define NT 6000        // training rows
#define QV 0.22360679774997896f   // sqrt(5)/sig, sig=10
#define KE 0.016666666666666666f  // 5/(3*sig^2) = 1/60

#define TBLK 148       // blocks in main kernel (one per SM)
#define WARPS 16       // warps per block
#define MSUB 4         // molecules per warp (16*4 = 64)
#define KCH 9          // p-chunks per lane (9*32 = 288 >= 276)

// Static device scratch (no allocation allowed)
__device__ float g_qxs[NM * NP];            // q * xs[m][p]
__device__ float g_xs3[NM * NP];            // xs^3
__device__ float g_Fxp[(size_t)TBLK * NM * NP]; // per-block partial F  (~10.5 MB)
__device__ float g_Ep[TBLK * NM];           // per-block partial E

// map pair index p -> (i, j) with i > j, tril row-major order
__device__ __forceinline__ void pair_ij(int p, int& i, int& j) {
    int ii = (int)((1.0f + sqrtf(1.0f + 8.0f * (float)p)) * 0.5f);
    while (ii * (ii - 1) / 2 > p) ii--;
    while ((ii + 1) * ii / 2 <= p) ii++;
    i = ii;
    j = p - ii * (ii - 1) / 2;
}

// ---------------- Kernel 0: descriptors per molecule ----------------
__global__ void prep_kernel(const float* __restrict__ Rs) {
    int m = blockIdx.x;
    int p = threadIdx.x;
    if (p >= NP) return;
    int i, j;
    pair_ij(p, i, j);
    float dx = Rs[(m * NA + i) * 3 + 0] - Rs[(m * NA + j) * 3 + 0];
    float dy = Rs[(m * NA + i) * 3 + 1] - Rs[(m * NA + j) * 3 + 1];
    float dz = Rs[(m * NA + i) * 3 + 2] - Rs[(m * NA + j) * 3 + 2];
    float d = sqrtf(dx * dx + dy * dy + dz * dz);
    float xs = 1.0f / d;
    g_qxs[m * NP + p] = QV * xs;
    g_xs3[m * NP + p] = xs * xs * xs;
}

// ---------------- Kernel 1: main M x T x P contraction ----------------
__global__ __launch_bounds__(WARPS * 32, 1)
void main_kernel(const float* __restrict__ xt_g, const float* __restrict__ jx_g) {
    const int warp = threadIdx.x >> 5;
    const int lane = threadIdx.x & 31;
    const int m0 = warp * MSUB;

    const int tchunk = (NT + TBLK - 1) / TBLK;   // 41
    const int t0 = blockIdx.x * tchunk;
    const int t1 = min(NT, t0 + tchunk);

    float qxs[MSUB][KCH];
    float Fa[MSUB][KCH];
    float Ea[MSUB];

    #pragma unroll
    for (int mi = 0; mi < MSUB; mi++) {
        Ea[mi] = 0.0f;
        #pragma unroll
        for (int k = 0; k < KCH; k++) {
            int p = lane + 32 * k;
            qxs[mi][k] = (p < NP) ? g_qxs[(m0 + mi) * NP + p] : 0.0f;
            Fa[mi][k] = 0.0f;
        }
    }

    for (int t = t0; t < t1; t++) {
        const float* __restrict__ xr = xt_g + (size_t)t * NP;
        const float* __restrict__ jr = jx_g + (size_t)t * NP;
        float xtl[KCH], jxl[KCH];
        #pragma unroll
        for (int k = 0; k < KCH; k++) {
            int p = lane + 32 * k;
            bool v = (p < NP);
            xtl[k] = v ? __ldg(xr + p) : 0.0f;
            jxl[k] = v ? __ldg(jr + p) : 0.0f;
        }

        #pragma unroll
        for (int mi = 0; mi < MSUB; mi++) {
            float d[KCH];
            float sq = 0.0f, dt = 0.0f;
            #pragma unroll
            for (int k = 0; k < KCH; k++) {
                d[k] = fmaf(-QV, xtl[k], qxs[mi][k]);  // x_diff
                sq = fmaf(d[k], d[k], sq);
                dt = fmaf(d[k], jxl[k], dt);
            }
            // warp butterfly reduction of (sq, dt) -> all lanes hold result
            #pragma unroll
            for (int o = 16; o > 0; o >>= 1) {
                sq += __shfl_xor_sync(0xffffffffu, sq, o);
                dt += __shfl_xor_sync(0xffffffffu, dt, o);
            }
            float xd = sqrtf(sq);                  // x_dist
            float e  = KE * expf(-xd);             // exp_xs
            float a  = e * dt;                     // exp_xs * dot
            float b  = e * (1.0f + xd);            // exp1
            #pragma unroll
            for (int k = 0; k < KCH; k++) {
                Fa[mi][k] = fmaf(a, d[k], Fa[mi][k]);     // F1 part
                Fa[mi][k] = fmaf(-b, jxl[k], Fa[mi][k]);  // -F2 part
            }
            Ea[mi] = fmaf(b, dt, Ea[mi]);          // exp1 * dot
        }
    }

    // deterministic per-block partials (no atomics)
    float* fout = g_Fxp + (size_t)blockIdx.x * NM * NP;
    #pragma unroll
    for (int mi = 0; mi < MSUB; mi++) {
        #pragma unroll
        for (int k = 0; k < KCH; k++) {
            int p = lane + 32 * k;
            if (p < NP) fout[(m0 + mi) * NP + p] = Fa[mi][k];
        }
        if (lane == 0) g_Ep[blockIdx.x * NM + (m0 + mi)] = Ea[mi];
    }
}

// ---------------- Kernel 2: reduce partials, scatter forces, energies ----------------
__global__ void final_kernel(const float* __restrict__ Rs, float* __restrict__ out) {
    __shared__ float Fxs[NP];  // Fs_x for this molecule
    const int m = blockIdx.x;
    const int tid = threadIdx.x;

    if (tid < NP) {
        float s = 0.0f;
        for (int b = 0; b < TBLK; b++)           // fixed order: deterministic
            s += g_Fxp[(size_t)b * NM * NP + m * NP + tid];
        Fxs[tid] = s * g_xs3[m * NP + tid];
    }
    __syncthreads();

    if (tid < NA * 3) {
        int a = tid / 3, c = tid % 3;
        float Ra = Rs[(m * NA + a) * 3 + c];
        float acc = 0.0f;
        #pragma unroll
        for (int bb = 0; bb < NA; bb++) {
            if (bb == a) continue;
            int hi = (a > bb) ? a : bb;
            int lo = (a > bb) ? bb : a;
            int p = hi * (hi - 1) / 2 + lo;
            float Rb = Rs[(m * NA + bb) * 3 + c];
            acc += (Rb - Ra) * Fxs[p];           // sum_b (R[b]-R[a]) * mult[b,a]
        }
        out[NM + m * NA * 3 + tid] = acc;        // Fs (STD = 1)
    }

    if (tid == 0) {
        float e = 0.0f;
        for (int b = 0; b < TBLK; b++) e += g_Ep[b * NM + m];
        out[m] = e / QV;                         // Es = sum/q * STD + C
    }
}

extern "C" void kernel_launch(void* const* d_in, const int* in_sizes, int n_in,
                              void* d_out, int out_size) {
    const float* Rs = (const float*)d_in[0];        // [64, 24, 3]
    const float* xs_train = (const float*)d_in[1];  // [6000, 276]
    const float* Jx = (const float*)d_in[2];        // [6000, 276]
    float* out = (float*)d_out;                     // [64 Es] ++ [64*24*3 Fs]

    prep_kernel<<<NM, 288>>>(Rs);
    main_kernel<<<TBLK, WARPS * 32>>>(xs_train, Jx);
    final_kernel<<<NM, 288>>>(Rs, out);
}